// round 3
// baseline (speedup 1.0000x reference)
#include <cuda_runtime.h>
#include <math.h>

// Problem constants
#define BATCH 8
#define CHAN  256
#define HH    512
#define WW    512
#define POOL  16
#define PH    (HH / POOL)          // 32
#define PW    (WW / POOL)          // 32
#define NPC   (BATCH * PH * PW)    // 8192 pooled elems per channel
#define GRID  (BATCH * CHAN * PH)  // 65536 blocks

// Per-channel moment accumulators: [c][5] = {S1, S2, S11, S22, S12}
// Zero-initialized at module load; the finalizing (last) block re-zeroes them
// after consuming, so every graph replay starts from zeros. Same for g_done.
__device__ float g_acc[CHAN * 5];
__device__ unsigned int g_done;

// One block per (b, c, ph). 256 threads.
// Thread t: rowpar = t>>7 (0/1), colg = t&127 (float4 group along W).
// 8 iterations over row pairs -> covers 16 raw rows x 512 cols.
// Each thread's 8 float4s (32 floats) all belong to pooled column colg>>2.
// The last block to finish also performs the finalize (per-channel corr ->
// scalar loss), eliminating a serial second kernel launch.
__global__ void __launch_bounds__(256, 8)
pool_stats_kernel(const float* __restrict__ f1, const float* __restrict__ f2,
                  float* __restrict__ out) {
    const int blk = blockIdx.x;
    const int ph = blk & (PH - 1);          // fastest: contiguous memory across blocks
    const int c  = (blk >> 5) & (CHAN - 1);
    const int b  = blk >> 13;

    const int t = threadIdx.x;
    const int rowpar = t >> 7;     // 0 or 1
    const int colg   = t & 127;    // float4 column group 0..127

    const size_t base = (((size_t)(b * CHAN + c)) * HH + (size_t)ph * POOL) * WW;
    const float4* __restrict__ p1 = (const float4*)(f1 + base);
    const float4* __restrict__ p2 = (const float4*)(f2 + base);

    float a1 = 0.0f, a2 = 0.0f;
#pragma unroll
    for (int it = 0; it < 8; it++) {
        const int row = rowpar + 2 * it;
        const float4 v1 = __ldcs(&p1[row * (WW / 4) + colg]);   // streaming: no reuse
        const float4 v2 = __ldcs(&p2[row * (WW / 4) + colg]);
        a1 += (v1.x + v1.y) + (v1.z + v1.w);
        a2 += (v2.x + v2.y) + (v2.z + v2.w);
    }

    __shared__ float s1[256];
    __shared__ float s2[256];
    __shared__ bool s_last;
    s1[t] = a1;
    s2[t] = a2;
    __syncthreads();

    if (t < PW) {  // 32 threads, one per pooled column (warp 0)
        float q1 = 0.0f, q2 = 0.0f;
#pragma unroll
        for (int q = 0; q < 4; q++) {
            q1 += s1[4 * t + q] + s1[128 + 4 * t + q];
            q2 += s2[4 * t + q] + s2[128 + 4 * t + q];
        }
        const float pv1 = q1 * (1.0f / 256.0f);   // pooled value f1
        const float pv2 = q2 * (1.0f / 256.0f);   // pooled value f2

        float m0 = pv1;
        float m1v = pv2;
        float m2 = pv1 * pv1;
        float m3 = pv2 * pv2;
        float m4 = pv1 * pv2;

#pragma unroll
        for (int off = 16; off > 0; off >>= 1) {
            m0  += __shfl_down_sync(0xffffffffu, m0,  off);
            m1v += __shfl_down_sync(0xffffffffu, m1v, off);
            m2  += __shfl_down_sync(0xffffffffu, m2,  off);
            m3  += __shfl_down_sync(0xffffffffu, m3,  off);
            m4  += __shfl_down_sync(0xffffffffu, m4,  off);
        }
        if (t == 0) {
            atomicAdd(&g_acc[c * 5 + 0], m0);
            atomicAdd(&g_acc[c * 5 + 1], m1v);
            atomicAdd(&g_acc[c * 5 + 2], m2);
            atomicAdd(&g_acc[c * 5 + 3], m3);
            atomicAdd(&g_acc[c * 5 + 4], m4);
            // Publish this block's moment contributions, then signal done.
            __threadfence();
            const unsigned int prev = atomicAdd(&g_done, 1u);
            s_last = (prev == (unsigned int)(GRID - 1));
        }
    }
    __syncthreads();

    // ---- Last block finalizes: 256 threads = 256 channels ----
    if (s_last) {
        const int ch = t;
        const float n = (float)NPC;

        // L2-coherent reads of the atomically-accumulated moments.
        const float v1s  = atomicAdd(&g_acc[ch * 5 + 0], 0.0f);
        const float v2s  = atomicAdd(&g_acc[ch * 5 + 1], 0.0f);
        const float v11  = atomicAdd(&g_acc[ch * 5 + 2], 0.0f);
        const float v22  = atomicAdd(&g_acc[ch * 5 + 3], 0.0f);
        const float v12  = atomicAdd(&g_acc[ch * 5 + 4], 0.0f);

        const float mA = v1s / n;
        const float mB = v2s / n;
        const float cov = v12 / n - mA * mB;                 // biased covariance
        const float ssd1 = v11 - v1s * v1s / n;              // sum squared deviations
        const float ssd2 = v22 - v2s * v2s / n;
        const float std1 = sqrtf(fmaxf(ssd1, 0.0f) / (n - 1.0f));  // unbiased std
        const float std2 = sqrtf(fmaxf(ssd2, 0.0f) / (n - 1.0f));
        const float corr = cov / (std1 * std2 + 1e-8f);
        const float a = fabsf(corr);

        // Reuse s1 as the reduction buffer (all prior uses are behind syncthreads).
        s1[t] = a;
        __syncthreads();
#pragma unroll
        for (int s = CHAN / 2; s > 0; s >>= 1) {
            if (t < s) s1[t] += s1[t + s];
            __syncthreads();
        }
        if (t == 0) {
            out[0] = 1.0f - s1[0] / (float)CHAN;
            g_done = 0u;  // reset for next graph replay
        }
        // Reset moment accumulators for next replay.
#pragma unroll
        for (int q = 0; q < 5; q++) g_acc[ch * 5 + q] = 0.0f;
    }
}

extern "C" void kernel_launch(void* const* d_in, const int* in_sizes, int n_in,
                              void* d_out, int out_size) {
    const float* f1 = (const float*)d_in[0];
    const float* f2 = (const float*)d_in[1];
    float* out = (float*)d_out;

    pool_stats_kernel<<<GRID, 256>>>(f1, f2, out);
}

// round 4
// speedup vs baseline: 1.0156x; 1.0156x over previous
#include <cuda_runtime.h>
#include <math.h>

// Problem constants
#define BATCH 8
#define CHAN  256
#define HH    512
#define WW    512
#define POOL  16
#define PH    (HH / POOL)          // 32
#define PW    (WW / POOL)          // 32
#define NPC   (BATCH * PH * PW)    // 8192 pooled elems per channel
#define GRID  (BATCH * CHAN * PH)  // 65536 blocks

// Per-channel moment accumulators: [c][5] = {S1, S2, S11, S22, S12}
// Zero-initialized at module load; finalize_kernel re-zeroes after consuming,
// so every graph replay (and the initial correctness call) starts from zeros.
__device__ float g_acc[CHAN * 5];

// One block per (b, c, ph). 256 threads.
// Thread t: rowpar = t>>7 (0/1), colg = t&127 (float4 group along W).
// 8 iterations over row pairs -> covers 16 raw rows x 512 cols.
// Each thread's 8 float4s (32 floats) all belong to pooled column colg>>2.
__global__ void __launch_bounds__(256, 8)
pool_stats_kernel(const float* __restrict__ f1, const float* __restrict__ f2) {
    const int blk = blockIdx.x;
    const int ph = blk & (PH - 1);          // fastest: contiguous memory across blocks
    const int c  = (blk >> 5) & (CHAN - 1);
    const int b  = blk >> 13;

    const int t = threadIdx.x;
    const int rowpar = t >> 7;     // 0 or 1
    const int colg   = t & 127;    // float4 column group 0..127

    const size_t base = (((size_t)(b * CHAN + c)) * HH + (size_t)ph * POOL) * WW;
    const float4* __restrict__ p1 = (const float4*)(f1 + base);
    const float4* __restrict__ p2 = (const float4*)(f2 + base);

    float a1 = 0.0f, a2 = 0.0f;
#pragma unroll
    for (int it = 0; it < 8; it++) {
        const int row = rowpar + 2 * it;
        const float4 v1 = __ldcs(&p1[row * (WW / 4) + colg]);   // streaming: no reuse
        const float4 v2 = __ldcs(&p2[row * (WW / 4) + colg]);
        a1 += (v1.x + v1.y) + (v1.z + v1.w);
        a2 += (v2.x + v2.y) + (v2.z + v2.w);
    }

    __shared__ float s1[256];
    __shared__ float s2[256];
    s1[t] = a1;
    s2[t] = a2;
    __syncthreads();

    if (t < PW) {  // 32 threads, one per pooled column (warp 0)
        float q1 = 0.0f, q2 = 0.0f;
#pragma unroll
        for (int q = 0; q < 4; q++) {
            q1 += s1[4 * t + q] + s1[128 + 4 * t + q];
            q2 += s2[4 * t + q] + s2[128 + 4 * t + q];
        }
        const float pv1 = q1 * (1.0f / 256.0f);   // pooled value f1
        const float pv2 = q2 * (1.0f / 256.0f);   // pooled value f2

        float m0 = pv1;
        float m1v = pv2;
        float m2 = pv1 * pv1;
        float m3 = pv2 * pv2;
        float m4 = pv1 * pv2;

#pragma unroll
        for (int off = 16; off > 0; off >>= 1) {
            m0  += __shfl_down_sync(0xffffffffu, m0,  off);
            m1v += __shfl_down_sync(0xffffffffu, m1v, off);
            m2  += __shfl_down_sync(0xffffffffu, m2,  off);
            m3  += __shfl_down_sync(0xffffffffu, m3,  off);
            m4  += __shfl_down_sync(0xffffffffu, m4,  off);
        }
        if (t == 0) {
            atomicAdd(&g_acc[c * 5 + 0], m0);
            atomicAdd(&g_acc[c * 5 + 1], m1v);
            atomicAdd(&g_acc[c * 5 + 2], m2);
            atomicAdd(&g_acc[c * 5 + 3], m3);
            atomicAdd(&g_acc[c * 5 + 4], m4);
        }
    }
    // All moment contributions are published; allow the dependent finalize
    // grid to launch while remaining blocks drain. Memory ops before this
    // trigger are visible to the dependent grid after its
    // cudaGridDependencySynchronize().
    cudaTriggerProgrammaticLaunchCompletion();
}

__global__ void finalize_kernel(float* __restrict__ out) {
    const int c = threadIdx.x;  // 256 threads, one per channel

    // Wait for all pool_stats blocks to trigger (PDL); their atomics to
    // g_acc are then visible.
    cudaGridDependencySynchronize();

    const float n = (float)NPC;

    const float s1v = g_acc[c * 5 + 0];
    const float s2v = g_acc[c * 5 + 1];
    const float s11 = g_acc[c * 5 + 2];
    const float s22 = g_acc[c * 5 + 3];
    const float s12 = g_acc[c * 5 + 4];

    const float mA = s1v / n;
    const float mB = s2v / n;
    const float cov = s12 / n - mA * mB;                 // biased covariance
    const float ssd1 = s11 - s1v * s1v / n;              // sum squared deviations
    const float ssd2 = s22 - s2v * s2v / n;
    const float std1 = sqrtf(fmaxf(ssd1, 0.0f) / (n - 1.0f));  // unbiased std
    const float std2 = sqrtf(fmaxf(ssd2, 0.0f) / (n - 1.0f));
    const float corr = cov / (std1 * std2 + 1e-8f);
    const float a = fabsf(corr);

    __shared__ float red[CHAN];
    red[c] = a;
    __syncthreads();
#pragma unroll
    for (int s = CHAN / 2; s > 0; s >>= 1) {
        if (c < s) red[c] += red[c + s];
        __syncthreads();
    }
    if (c == 0) out[0] = 1.0f - red[0] / (float)CHAN;

    // Re-zero the accumulators for the next graph replay.
#pragma unroll
    for (int q = 0; q < 5; q++) g_acc[c * 5 + q] = 0.0f;
}

extern "C" void kernel_launch(void* const* d_in, const int* in_sizes, int n_in,
                              void* d_out, int out_size) {
    const float* f1 = (const float*)d_in[0];
    const float* f2 = (const float*)d_in[1];
    float* out = (float*)d_out;

    pool_stats_kernel<<<GRID, 256>>>(f1, f2);

    // Finalize with programmatic dependent launch: its launch latency and
    // prologue overlap the main kernel's tail waves.
    cudaLaunchConfig_t cfg = {};
    cfg.gridDim = dim3(1, 1, 1);
    cfg.blockDim = dim3(CHAN, 1, 1);
    cfg.dynamicSmemBytes = 0;
    cfg.stream = 0;
    cudaLaunchAttribute attrs[1];
    attrs[0].id = cudaLaunchAttributeProgrammaticStreamSerialization;
    attrs[0].val.programmaticStreamSerializationAllowed = 1;
    cfg.attrs = attrs;
    cfg.numAttrs = 1;
    cudaLaunchKernelEx(&cfg, finalize_kernel, out);
}